// round 1
// baseline (speedup 1.0000x reference)
#include <cuda_runtime.h>
#include <math.h>

// Problem constants
#define BB 4096
#define DD 256
#define TT 64

// ---------------- scratch (__device__ globals; no allocations allowed) ----------------
__device__ __align__(16) float g_q0sel[BB * DD];
__device__ __align__(16) float g_r0sel[BB * DD];
__device__ __align__(16) float g_xg [BB * 768];
__device__ __align__(16) float g_xqs[BB * 512];
__device__ __align__(16) float g_xrs[BB * 512];
__device__ __align__(16) float g_xpl[BB * 512];
__device__ __align__(16) float g_xe [BB * 768];
__device__ __align__(16) float g_c  [BB * DD];
__device__ int g_selrow[BB];
__device__ int g_qmidx [BB];

// ---------------- prep: qm_idx, gathers, xg = [q0sel | r0sel | U] ----------------
__global__ void prep_kernel(const float* __restrict__ U, const float* __restrict__ qmask,
                            const float* __restrict__ q0, const float* __restrict__ r0) {
    int i = blockIdx.x * 256 + threadIdx.x;  // 0 .. B*256-1
    int b = i >> 8, d = i & 255;
    int qm = (qmask[b * 2 + 1] > qmask[b * 2]) ? 1 : 0;
    if (d == 0) { g_qmidx[b] = qm; g_selrow[b] = b * 2 + qm; }
    float q = q0[(size_t)(b * 2 + qm) * DD + d];
    float r = r0[(size_t)(b * 2 + qm) * DD + d];
    g_q0sel[i] = q;
    g_r0sel[i] = r;
    g_xg[(size_t)b * 768 + d]       = q;
    g_xg[(size_t)b * 768 + 256 + d] = r;
    g_xg[(size_t)b * 768 + 512 + d] = U[i];
}

// ---------------- attention: one pass over g_hist (SMEM-cached per b) ----------------
__global__ void att_kernel(const float* __restrict__ gh, const float* __restrict__ attw,
                           float* __restrict__ cvec, float* __restrict__ alpha_out) {
    extern __shared__ float sh[];           // TT * DD floats = 64 KB
    __shared__ float s_aw[DD];
    __shared__ float s_scale[TT];
    __shared__ float s_alpha[TT];
    int b = blockIdx.x, tid = threadIdx.x;
    s_aw[tid] = attw[tid];
    for (int t = 0; t < TT; t++)
        sh[t * DD + tid] = gh[((size_t)t * BB + b) * DD + tid];
    __syncthreads();

    int w = tid >> 5, lane = tid & 31;
    for (int t = w; t < TT; t += 8) {
        float s = 0.f;
        #pragma unroll
        for (int i = 0; i < 8; i++) s += sh[t * DD + lane + i * 32] * s_aw[lane + i * 32];
        #pragma unroll
        for (int o = 16; o > 0; o >>= 1) s += __shfl_down_sync(0xffffffffu, s, o);
        if (lane == 0) s_scale[t] = s;
    }
    __syncthreads();

    if (w == 0) {
        float v0 = s_scale[lane], v1 = s_scale[lane + 32];
        float m = fmaxf(v0, v1);
        #pragma unroll
        for (int o = 16; o > 0; o >>= 1) m = fmaxf(m, __shfl_xor_sync(0xffffffffu, m, o));
        float e0 = expf(v0 - m), e1 = expf(v1 - m);
        float s = e0 + e1;
        #pragma unroll
        for (int o = 16; o > 0; o >>= 1) s += __shfl_xor_sync(0xffffffffu, s, o);
        float inv = 1.f / s;
        s_alpha[lane]      = e0 * inv;
        s_alpha[lane + 32] = e1 * inv;
        alpha_out[(size_t)b * TT + lane]      = e0 * inv;
        alpha_out[(size_t)b * TT + lane + 32] = e1 * inv;
    }
    __syncthreads();

    float acc = 0.f;
    for (int t = 0; t < TT; t++) acc += s_alpha[t] * sh[t * DD + tid];
    cvec[(size_t)b * DD + tid] = acc;
}

// ---------------- fused GRU: gi = X@Wih^T, gh = H@Whh^T, gates, write ----------------
// Block computes out[64 rows x 64 cols]; 4 accumulator groups (r, z, in, hn).
// xshift: x_row = out_row >> xshift (0 normally; 1 for qs where X is per-b).
// out_rows: optional row-index indirection for scatter (ql/rs), else identity.
__global__ __launch_bounds__(256, 2) void gru_kernel(
    const float* __restrict__ X, int K, int xshift,
    const float* __restrict__ H,
    const float* __restrict__ Wih, const float* __restrict__ Whh,
    const float* __restrict__ bih, const float* __restrict__ bhh,
    float* __restrict__ Out, const int* __restrict__ out_rows)
{
    __shared__ __align__(16) float Xs[16][68];
    __shared__ __align__(16) float Ws[3][16][68];

    float ar[4][4] = {}, az[4][4] = {}, an[4][4] = {}, ah[4][4] = {};

    int tid = threadIdx.x;
    int tx = tid & 15, ty = tid >> 4;
    int row0 = blockIdx.x * 64;
    int c0   = blockIdx.y * 64;
    int lm = tid >> 2;          // 0..63 (row for X-tile / weight row)
    int lk = (tid & 3) * 4;     // k segment start

    // ---- loop 1: input GEMM (gates r, z, in) over K ----
    for (int k0 = 0; k0 < K; k0 += 16) {
        {
            int xr = (row0 + lm) >> xshift;
            float4 v = *(const float4*)(X + (size_t)xr * K + k0 + lk);
            Xs[lk + 0][lm] = v.x; Xs[lk + 1][lm] = v.y;
            Xs[lk + 2][lm] = v.z; Xs[lk + 3][lm] = v.w;
        }
        #pragma unroll
        for (int g = 0; g < 3; g++) {
            float4 v = *(const float4*)(Wih + (size_t)(g * 256 + c0 + lm) * K + k0 + lk);
            Ws[g][lk + 0][lm] = v.x; Ws[g][lk + 1][lm] = v.y;
            Ws[g][lk + 2][lm] = v.z; Ws[g][lk + 3][lm] = v.w;
        }
        __syncthreads();
        #pragma unroll 4
        for (int kk = 0; kk < 16; kk++) {
            float4 xa = *(const float4*)&Xs[kk][ty * 4];
            float4 wr = *(const float4*)&Ws[0][kk][tx * 4];
            float4 wz = *(const float4*)&Ws[1][kk][tx * 4];
            float4 wn = *(const float4*)&Ws[2][kk][tx * 4];
            float xv[4]  = {xa.x, xa.y, xa.z, xa.w};
            float wrv[4] = {wr.x, wr.y, wr.z, wr.w};
            float wzv[4] = {wz.x, wz.y, wz.z, wz.w};
            float wnv[4] = {wn.x, wn.y, wn.z, wn.w};
            #pragma unroll
            for (int i = 0; i < 4; i++)
                #pragma unroll
                for (int j = 0; j < 4; j++) {
                    ar[i][j] += xv[i] * wrv[j];
                    az[i][j] += xv[i] * wzv[j];
                    an[i][j] += xv[i] * wnv[j];
                }
        }
        __syncthreads();
    }

    // ---- loop 2: hidden GEMM (gates r, z, hn) over 256 ----
    for (int k0 = 0; k0 < 256; k0 += 16) {
        {
            float4 v = *(const float4*)(H + (size_t)(row0 + lm) * 256 + k0 + lk);
            Xs[lk + 0][lm] = v.x; Xs[lk + 1][lm] = v.y;
            Xs[lk + 2][lm] = v.z; Xs[lk + 3][lm] = v.w;
        }
        #pragma unroll
        for (int g = 0; g < 3; g++) {
            float4 v = *(const float4*)(Whh + (size_t)(g * 256 + c0 + lm) * 256 + k0 + lk);
            Ws[g][lk + 0][lm] = v.x; Ws[g][lk + 1][lm] = v.y;
            Ws[g][lk + 2][lm] = v.z; Ws[g][lk + 3][lm] = v.w;
        }
        __syncthreads();
        #pragma unroll 4
        for (int kk = 0; kk < 16; kk++) {
            float4 xa = *(const float4*)&Xs[kk][ty * 4];
            float4 wr = *(const float4*)&Ws[0][kk][tx * 4];
            float4 wz = *(const float4*)&Ws[1][kk][tx * 4];
            float4 wn = *(const float4*)&Ws[2][kk][tx * 4];
            float xv[4]  = {xa.x, xa.y, xa.z, xa.w};
            float wrv[4] = {wr.x, wr.y, wr.z, wr.w};
            float wzv[4] = {wz.x, wz.y, wz.z, wz.w};
            float wnv[4] = {wn.x, wn.y, wn.z, wn.w};
            #pragma unroll
            for (int i = 0; i < 4; i++)
                #pragma unroll
                for (int j = 0; j < 4; j++) {
                    ar[i][j] += xv[i] * wrv[j];
                    az[i][j] += xv[i] * wzv[j];
                    ah[i][j] += xv[i] * wnv[j];
                }
        }
        __syncthreads();
    }

    // ---- epilogue: gates + output ----
    #pragma unroll
    for (int j = 0; j < 4; j++) {
        int col = c0 + tx * 4 + j;
        float br  = bih[col]       + bhh[col];
        float bz  = bih[256 + col] + bhh[256 + col];
        float bin = bih[512 + col];
        float bhn = bhh[512 + col];
        #pragma unroll
        for (int i = 0; i < 4; i++) {
            int mg = row0 + ty * 4 + i;
            float r = 1.f / (1.f + expf(-(ar[i][j] + br)));
            float z = 1.f / (1.f + expf(-(az[i][j] + bz)));
            float n = tanhf(an[i][j] + bin + r * (ah[i][j] + bhn));
            float h = H[(size_t)mg * 256 + col];
            float o = (1.f - z) * n + z * h;
            int orow = out_rows ? out_rows[mg] : mg;
            Out[(size_t)orow * 256 + col] = o;
        }
    }
}

// ---------------- small builders ----------------
// dst[b, 0:256] = A[b], dst[b, 256:512] = Bsrc[b]   (grid: (B, 2) x 256)
__global__ void build2_kernel(float* __restrict__ dst, const float* __restrict__ A,
                              const float* __restrict__ Bsrc) {
    int b = blockIdx.x, half = blockIdx.y, d = threadIdx.x;
    float v = half ? Bsrc[(size_t)b * 256 + d] : A[(size_t)b * 256 + d];
    dst[(size_t)b * 512 + half * 256 + d] = v;
}

// xpl[b] = [ qbase[selrow(b)] | U[b] ]
__global__ void build_xpl_kernel(float* __restrict__ dst, const float* __restrict__ qbase,
                                 const float* __restrict__ U) {
    int b = blockIdx.x, half = blockIdx.y, d = threadIdx.x;
    float v = half ? U[(size_t)b * 256 + d]
                   : qbase[(size_t)g_selrow[b] * 256 + d];
    dst[(size_t)b * 512 + half * 256 + d] = v;
}

// xe[b] = [ U[b] | qbase[selrow(b)] | gv[b] ]
__global__ void build_xe_kernel(float* __restrict__ dst, const float* __restrict__ U,
                                const float* __restrict__ qbase, const float* __restrict__ gv) {
    int b = blockIdx.x, seg = blockIdx.y, d = threadIdx.x;
    float v;
    if (seg == 0)      v = U[(size_t)b * 256 + d];
    else if (seg == 1) v = qbase[(size_t)g_selrow[b] * 256 + d];
    else               v = gv[(size_t)b * 256 + d];
    dst[(size_t)b * 768 + seg * 256 + d] = v;
}

// zero the non-selected p rows of r_
__global__ void zero_r_kernel(float* __restrict__ rbase) {
    int i = blockIdx.x * 256 + threadIdx.x;  // B*256
    int b = i >> 8, d = i & 255;
    int other = b * 2 + (1 - g_qmidx[b]);
    rbase[(size_t)other * 256 + d] = 0.f;
}

// ---------------- launch ----------------
extern "C" void kernel_launch(void* const* d_in, const int* in_sizes, int n_in,
                              void* d_out, int out_size) {
    const float* U      = (const float*)d_in[0];
    const float* qmask  = (const float*)d_in[1];
    const float* g_hist = (const float*)d_in[2];
    const float* q0     = (const float*)d_in[3];
    const float* r0     = (const float*)d_in[4];
    const float* e0     = (const float*)d_in[5];
    const float* g_wih  = (const float*)d_in[6];
    const float* g_whh  = (const float*)d_in[7];
    const float* g_bih  = (const float*)d_in[8];
    const float* g_bhh  = (const float*)d_in[9];
    const float* p_wih  = (const float*)d_in[10];
    const float* p_whh  = (const float*)d_in[11];
    const float* p_bih  = (const float*)d_in[12];
    const float* p_bhh  = (const float*)d_in[13];
    const float* pl_wih = (const float*)d_in[14];
    const float* pl_whh = (const float*)d_in[15];
    const float* pl_bih = (const float*)d_in[16];
    const float* pl_bhh = (const float*)d_in[17];
    const float* r_wih  = (const float*)d_in[18];
    const float* r_whh  = (const float*)d_in[19];
    const float* r_bih  = (const float*)d_in[20];
    const float* r_bhh  = (const float*)d_in[21];
    const float* e_wih  = (const float*)d_in[22];
    const float* e_whh  = (const float*)d_in[23];
    const float* e_bih  = (const float*)d_in[24];
    const float* e_bhh  = (const float*)d_in[25];
    const float* att_w  = (const float*)d_in[26];

    float* out = (float*)d_out;
    float* o_g = out;                    // (B, 256)
    float* o_q = out + 1048576;          // (B, 2, 256)
    float* o_r = out + 3145728;          // (B, 2, 256)
    float* o_e = out + 5242880;          // (B, 256)
    float* o_a = out + 6291456;          // (B, 1, 64)

    // scratch pointers
    void *p_xg, *p_xqs, *p_xrs, *p_xpl, *p_xe, *p_c, *p_q0sel, *p_r0sel, *p_selrow;
    cudaGetSymbolAddress(&p_xg,     g_xg);
    cudaGetSymbolAddress(&p_xqs,    g_xqs);
    cudaGetSymbolAddress(&p_xrs,    g_xrs);
    cudaGetSymbolAddress(&p_xpl,    g_xpl);
    cudaGetSymbolAddress(&p_xe,     g_xe);
    cudaGetSymbolAddress(&p_c,      g_c);
    cudaGetSymbolAddress(&p_q0sel,  g_q0sel);
    cudaGetSymbolAddress(&p_r0sel,  g_r0sel);
    cudaGetSymbolAddress(&p_selrow, g_selrow);

    float* xg    = (float*)p_xg;
    float* xqs   = (float*)p_xqs;
    float* xrs   = (float*)p_xrs;
    float* xpl   = (float*)p_xpl;
    float* xe    = (float*)p_xe;
    float* cvec  = (float*)p_c;
    float* q0sel = (float*)p_q0sel;
    float* r0sel = (float*)p_r0sel;
    int*   selrow = (int*)p_selrow;

    cudaFuncSetAttribute(att_kernel, cudaFuncAttributeMaxDynamicSharedMemorySize,
                         TT * DD * (int)sizeof(float));

    // 1) prep: qm_idx, gathers, xg
    prep_kernel<<<BB, 256>>>(U, qmask, q0, r0);

    // 2) attention -> c_, alpha_out  (independent of GRU chain)
    att_kernel<<<BB, 256, TT * DD * sizeof(float)>>>(g_hist, att_w, cvec, o_a);

    // 3) g GRU: x = xg (K=768), h = g_hist[63]
    gru_kernel<<<dim3(BB / 64, 4), 256>>>(xg, 768, 0,
        g_hist + (size_t)63 * BB * DD, g_wih, g_whh, g_bih, g_bhh, o_g, nullptr);

    // 4) qs GRU: x = [g_ | U] per-b (K=512, xshift=1), h = q0 flat, 8192 rows -> q_
    build2_kernel<<<dim3(BB, 2), 256>>>(xqs, o_g, U);
    gru_kernel<<<dim3(2 * BB / 64, 4), 256>>>(xqs, 512, 1,
        q0, p_wih, p_whh, p_bih, p_bhh, o_q, nullptr);

    // 5) rs GRU (selected rows only): x = [c_ | U], h = r0sel -> scatter into r_
    build2_kernel<<<dim3(BB, 2), 256>>>(xrs, cvec, U);
    gru_kernel<<<dim3(BB / 64, 4), 256>>>(xrs, 512, 0,
        r0sel, r_wih, r_whh, r_bih, r_bhh, o_r, selrow);
    zero_r_kernel<<<BB, 256>>>(o_r);

    // 6) ql GRU (selected rows only): x = [qs_sel | U], h = q0sel -> scatter into q_
    build_xpl_kernel<<<dim3(BB, 2), 256>>>(xpl, o_q, U);   // q_ still holds qs_ here
    gru_kernel<<<dim3(BB / 64, 4), 256>>>(xpl, 512, 0,
        q0sel, pl_wih, pl_whh, pl_bih, pl_bhh, o_q, selrow);

    // 7) e GRU: x = [U | sel(q_) | g_] (K=768), h = e0
    build_xe_kernel<<<dim3(BB, 3), 256>>>(xe, U, o_q, o_g);
    gru_kernel<<<dim3(BB / 64, 4), 256>>>(xe, 768, 0,
        e0, e_wih, e_whh, e_bih, e_bhh, o_e, nullptr);
}

// round 3
// speedup vs baseline: 1.5137x; 1.5137x over previous
#include <cuda_runtime.h>
#include <cuda_bf16.h>
#include <math.h>
#include <stdint.h>

#define BB 4096
#define DD 256
#define TT 64

// ================= PTX helpers (baseline ISA only: mma.sync / ldmatrix / cp.async) =====
__device__ __forceinline__ uint32_t smem_u32(const void* p) {
    uint32_t a;
    asm("{ .reg .u64 t; cvta.to.shared.u64 t, %1; cvt.u32.u64 %0, t; }" : "=r"(a) : "l"(p));
    return a;
}
__device__ __forceinline__ void cp16(uint32_t saddr, const void* g) {
    asm volatile("cp.async.cg.shared.global [%0], [%1], 16;" :: "r"(saddr), "l"(g));
}
__device__ __forceinline__ void ldsm4(uint32_t* r, uint32_t addr) {
    asm volatile("ldmatrix.sync.aligned.m8n8.x4.shared.b16 {%0,%1,%2,%3}, [%4];"
        : "=r"(r[0]), "=r"(r[1]), "=r"(r[2]), "=r"(r[3]) : "r"(addr));
}
__device__ __forceinline__ void mma16816(float* c, const uint32_t* a, uint32_t b0, uint32_t b1) {
    asm volatile("mma.sync.aligned.m16n8k16.row.col.f32.bf16.bf16.f32 "
        "{%0,%1,%2,%3}, {%4,%5,%6,%7}, {%8,%9}, {%0,%1,%2,%3};"
        : "+f"(c[0]), "+f"(c[1]), "+f"(c[2]), "+f"(c[3])
        : "r"(a[0]), "r"(a[1]), "r"(a[2]), "r"(a[3]), "r"(b0), "r"(b1));
}

// ================= scratch pool =================
static constexpr size_t SZ_XG  = (size_t)BB * 768 * 2;   // bf16 bytes
static constexpr size_t SZ_XS  = (size_t)BB * 512 * 2;
static constexpr size_t SZ_BD  = (size_t)BB * 256 * 2;
static constexpr size_t SZ_Q0  = (size_t)2 * BB * 256 * 2;
static constexpr size_t SZ_BDF = (size_t)BB * 256 * 4;   // f32 bytes

static constexpr size_t O_XG_H  = 0;
static constexpr size_t O_XG_L  = O_XG_H  + SZ_XG;
static constexpr size_t O_XE_H  = O_XG_L  + SZ_XG;
static constexpr size_t O_XE_L  = O_XE_H  + SZ_XG;
static constexpr size_t O_XQS_H = O_XE_L  + SZ_XG;
static constexpr size_t O_XQS_L = O_XQS_H + SZ_XS;
static constexpr size_t O_XRS_H = O_XQS_L + SZ_XS;
static constexpr size_t O_XRS_L = O_XRS_H + SZ_XS;
static constexpr size_t O_XPL_H = O_XRS_L + SZ_XS;
static constexpr size_t O_XPL_L = O_XPL_H + SZ_XS;
static constexpr size_t O_Q0_H  = O_XPL_L + SZ_XS;
static constexpr size_t O_Q0_L  = O_Q0_H  + SZ_Q0;
static constexpr size_t O_GH_H  = O_Q0_L  + SZ_Q0;
static constexpr size_t O_GH_L  = O_GH_H  + SZ_BD;
static constexpr size_t O_E0_H  = O_GH_L  + SZ_BD;
static constexpr size_t O_E0_L  = O_E0_H  + SZ_BD;
static constexpr size_t O_QS_H  = O_E0_L  + SZ_BD;   // q0sel bf16
static constexpr size_t O_QS_L  = O_QS_H  + SZ_BD;
static constexpr size_t O_RS_H  = O_QS_L  + SZ_BD;   // r0sel bf16
static constexpr size_t O_RS_L  = O_RS_H  + SZ_BD;
static constexpr size_t O_QSF   = O_RS_L  + SZ_BD;   // q0sel f32
static constexpr size_t O_RSF   = O_QSF   + SZ_BDF;
static constexpr size_t O_CV    = O_RSF   + SZ_BDF;  // cvec f32
static constexpr size_t SZ_W768 = (size_t)768 * 768 * 2;
static constexpr size_t SZ_W512 = (size_t)768 * 512 * 2;
static constexpr size_t SZ_W256 = (size_t)768 * 256 * 2;
static constexpr size_t O_WGIH_H = O_CV + SZ_BDF;
static constexpr size_t O_WGIH_L = O_WGIH_H + SZ_W768;
static constexpr size_t O_WGHH_H = O_WGIH_L + SZ_W768;
static constexpr size_t O_WGHH_L = O_WGHH_H + SZ_W256;
static constexpr size_t O_WPIH_H = O_WGHH_L + SZ_W256;
static constexpr size_t O_WPIH_L = O_WPIH_H + SZ_W512;
static constexpr size_t O_WPHH_H = O_WPIH_L + SZ_W512;
static constexpr size_t O_WPHH_L = O_WPHH_H + SZ_W256;
static constexpr size_t O_WLIH_H = O_WPHH_L + SZ_W256;
static constexpr size_t O_WLIH_L = O_WLIH_H + SZ_W512;
static constexpr size_t O_WLHH_H = O_WLIH_L + SZ_W512;
static constexpr size_t O_WLHH_L = O_WLHH_H + SZ_W256;
static constexpr size_t O_WRIH_H = O_WLHH_L + SZ_W256;
static constexpr size_t O_WRIH_L = O_WRIH_H + SZ_W512;
static constexpr size_t O_WRHH_H = O_WRIH_L + SZ_W512;
static constexpr size_t O_WRHH_L = O_WRHH_H + SZ_W256;
static constexpr size_t O_WEIH_H = O_WRHH_L + SZ_W256;
static constexpr size_t O_WEIH_L = O_WEIH_H + SZ_W768;
static constexpr size_t O_WEHH_H = O_WEIH_L + SZ_W768;
static constexpr size_t O_WEHH_L = O_WEHH_H + SZ_W256;
static constexpr size_t O_SELROW = O_WEHH_L + SZ_W256;
static constexpr size_t O_QMIDX  = O_SELROW + BB * 4;
static constexpr size_t POOL_SZ  = O_QMIDX + BB * 4;

__device__ __align__(1024) unsigned char g_pool[POOL_SZ];

// ================= small kernels =================
__device__ __forceinline__ void bsplit(float x, __nv_bfloat16* hp, __nv_bfloat16* lp, size_t i) {
    __nv_bfloat16 h = __float2bfloat16(x);
    hp[i] = h;
    lp[i] = __float2bfloat16(x - __bfloat162float(h));
}

__global__ void conv_kernel(const float* __restrict__ in, __nv_bfloat16* __restrict__ hi,
                            __nv_bfloat16* __restrict__ lo, int n) {
    int i = blockIdx.x * 256 + threadIdx.x;
    if (i < n) bsplit(in[i], hi, lo, i);
}

__global__ void prep_kernel(const float* __restrict__ U, const float* __restrict__ qmask,
                            const float* __restrict__ q0, const float* __restrict__ r0,
                            float* __restrict__ qsf, float* __restrict__ rsf,
                            __nv_bfloat16* qsh, __nv_bfloat16* qsl,
                            __nv_bfloat16* rsh, __nv_bfloat16* rsl,
                            __nv_bfloat16* xgh, __nv_bfloat16* xgl,
                            int* __restrict__ selrow, int* __restrict__ qmidx) {
    int i = blockIdx.x * 256 + threadIdx.x;
    int b = i >> 8, d = i & 255;
    int qm = (qmask[b * 2 + 1] > qmask[b * 2]) ? 1 : 0;
    if (d == 0) { qmidx[b] = qm; selrow[b] = b * 2 + qm; }
    float q = q0[(size_t)(b * 2 + qm) * DD + d];
    float r = r0[(size_t)(b * 2 + qm) * DD + d];
    float u = U[i];
    qsf[i] = q; rsf[i] = r;
    bsplit(q, qsh, qsl, i);
    bsplit(r, rsh, rsl, i);
    size_t o = (size_t)b * 768 + d;
    bsplit(q, xgh, xgl, o);
    bsplit(r, xgh, xgl, o + 256);
    bsplit(u, xgh, xgl, o + 512);
}

__global__ void build2b_kernel(__nv_bfloat16* __restrict__ dh, __nv_bfloat16* __restrict__ dl,
                               const float* __restrict__ A, const float* __restrict__ Bs) {
    int b = blockIdx.x, half = blockIdx.y, d = threadIdx.x;
    float v = half ? Bs[(size_t)b * 256 + d] : A[(size_t)b * 256 + d];
    bsplit(v, dh, dl, (size_t)b * 512 + half * 256 + d);
}

__global__ void build_xplb_kernel(__nv_bfloat16* __restrict__ dh, __nv_bfloat16* __restrict__ dl,
                                  const float* __restrict__ qbase, const float* __restrict__ U,
                                  const int* __restrict__ selrow) {
    int b = blockIdx.x, half = blockIdx.y, d = threadIdx.x;
    float v = half ? U[(size_t)b * 256 + d] : qbase[(size_t)selrow[b] * 256 + d];
    bsplit(v, dh, dl, (size_t)b * 512 + half * 256 + d);
}

__global__ void build_xeb_kernel(__nv_bfloat16* __restrict__ dh, __nv_bfloat16* __restrict__ dl,
                                 const float* __restrict__ U, const float* __restrict__ qbase,
                                 const float* __restrict__ gv, const int* __restrict__ selrow) {
    int b = blockIdx.x, seg = blockIdx.y, d = threadIdx.x;
    float v;
    if (seg == 0)      v = U[(size_t)b * 256 + d];
    else if (seg == 1) v = qbase[(size_t)selrow[b] * 256 + d];
    else               v = gv[(size_t)b * 256 + d];
    bsplit(v, dh, dl, (size_t)b * 768 + seg * 256 + d);
}

__global__ void zero_r_kernel(float* __restrict__ rbase, const int* __restrict__ qmidx) {
    int i = blockIdx.x * 256 + threadIdx.x;
    int b = i >> 8, d = i & 255;
    int other = b * 2 + (1 - qmidx[b]);
    rbase[(size_t)other * 256 + d] = 0.f;
}

// ================= attention =================
__global__ void att_kernel(const float* __restrict__ gh, const float* __restrict__ attw,
                           float* __restrict__ cvec, float* __restrict__ alpha_out) {
    extern __shared__ float sh[];
    __shared__ float s_aw[DD];
    __shared__ float s_scale[TT];
    __shared__ float s_alpha[TT];
    int b = blockIdx.x, tid = threadIdx.x;
    s_aw[tid] = attw[tid];
    for (int t = 0; t < TT; t++)
        sh[t * DD + tid] = gh[((size_t)t * BB + b) * DD + tid];
    __syncthreads();
    int w = tid >> 5, lane = tid & 31;
    for (int t = w; t < TT; t += 8) {
        float s = 0.f;
        #pragma unroll
        for (int i = 0; i < 8; i++) s += sh[t * DD + lane + i * 32] * s_aw[lane + i * 32];
        #pragma unroll
        for (int o = 16; o > 0; o >>= 1) s += __shfl_down_sync(0xffffffffu, s, o);
        if (lane == 0) s_scale[t] = s;
    }
    __syncthreads();
    if (w == 0) {
        float v0 = s_scale[lane], v1 = s_scale[lane + 32];
        float m = fmaxf(v0, v1);
        #pragma unroll
        for (int o = 16; o > 0; o >>= 1) m = fmaxf(m, __shfl_xor_sync(0xffffffffu, m, o));
        float e0 = expf(v0 - m), e1 = expf(v1 - m);
        float s = e0 + e1;
        #pragma unroll
        for (int o = 16; o > 0; o >>= 1) s += __shfl_xor_sync(0xffffffffu, s, o);
        float inv = 1.f / s;
        s_alpha[lane] = e0 * inv;
        s_alpha[lane + 32] = e1 * inv;
        alpha_out[(size_t)b * TT + lane] = e0 * inv;
        alpha_out[(size_t)b * TT + lane + 32] = e1 * inv;
    }
    __syncthreads();
    float acc = 0.f;
    for (int t = 0; t < TT; t++) acc += s_alpha[t] * sh[t * DD + tid];
    cvec[(size_t)b * DD + tid] = acc;
}

// ================= fused GRU via mma.sync (bf16 3-term split) =================
// Block: 64 rows x 64 out-cols. 8 warps = 4(m) x 2(n). Warp tile 16x32.
// Acc groups: 0=r, 1=z, 2=in, 3=hn. cp.async 2-stage pipeline, chunk K=32.
// Smem tile: [64 rows][40 bf16] (pad 8) -> 5120 B. 8 tiles/stage: Ahi,Alo,W(g,hl)x6.
#define TILE_SB 5120
#define STAGE_SB (8 * TILE_SB)   // 40960
#define GRU_SMEM (2 * STAGE_SB)  // 81920

__global__ __launch_bounds__(256, 2) void gru_mma_kernel(
    const __nv_bfloat16* __restrict__ Xhi, const __nv_bfloat16* __restrict__ Xlo,
    int K, int xshift,
    const __nv_bfloat16* __restrict__ Hhi, const __nv_bfloat16* __restrict__ Hlo,
    const float* __restrict__ Hf,
    const __nv_bfloat16* __restrict__ Wih_hi, const __nv_bfloat16* __restrict__ Wih_lo,
    const __nv_bfloat16* __restrict__ Whh_hi, const __nv_bfloat16* __restrict__ Whh_lo,
    const float* __restrict__ bih, const float* __restrict__ bhh,
    float* __restrict__ Out, const int* __restrict__ out_rows)
{
    extern __shared__ __align__(16) char dsm[];
    const uint32_t smb = smem_u32(dsm);

    const int tid = threadIdx.x;
    const int wid = tid >> 5, lane = tid & 31;
    const int warp_m = wid & 3, warp_n = wid >> 2;
    const int row0 = blockIdx.x * 64, c0 = blockIdx.y * 64;

    // global-load coords (per thread: one 16B vector per tile)
    const int lr = tid >> 2;            // 0..63 tile row
    const int lc = (tid & 3) * 8;       // elem col within chunk (0,8,16,24)
    const uint32_t st_off = (uint32_t)lr * 80 + (tid & 3) * 16;  // byte offset in tile

    const int nch0 = K / 32;
    const int ntot = nch0 + 8;

    float acc[4][16];
    #pragma unroll
    for (int g = 0; g < 4; g++)
        #pragma unroll
        for (int d = 0; d < 16; d++) acc[g][d] = 0.f;

    // ldmatrix per-lane address pieces (bytes)
    const uint32_t aoff = ((uint32_t)(warp_m * 16 + (lane & 7) + ((lane >> 3) & 1) * 8)) * 80
                        + (uint32_t)(lane >> 4) * 16;
    const uint32_t boff = ((uint32_t)(warp_n * 32 + (lane & 7) + (lane >> 4) * 8)) * 80
                        + (uint32_t)((lane >> 3) & 1) * 16;

    // ---- prefetch helper (macro-ish via lambda) ----
    auto prefetch = [&](int idx) {
        const __nv_bfloat16 *ah, *al, *wh, *wl;
        int ld, k0, sh;
        if (idx < nch0) { ah = Xhi; al = Xlo; wh = Wih_hi; wl = Wih_lo; ld = K;   k0 = idx * 32;          sh = xshift; }
        else            { ah = Hhi; al = Hlo; wh = Whh_hi; wl = Whh_lo; ld = 256; k0 = (idx - nch0) * 32; sh = 0; }
        uint32_t stg = smb + (uint32_t)(idx & 1) * STAGE_SB;
        int xr = (row0 + lr) >> sh;
        cp16(stg + 0 * TILE_SB + st_off, ah + (size_t)xr * ld + k0 + lc);
        cp16(stg + 1 * TILE_SB + st_off, al + (size_t)xr * ld + k0 + lc);
        #pragma unroll
        for (int g = 0; g < 3; g++) {
            int wr = g * 256 + c0 + lr;
            cp16(stg + (2 + g * 2) * TILE_SB + st_off, wh + (size_t)wr * ld + k0 + lc);
            cp16(stg + (3 + g * 2) * TILE_SB + st_off, wl + (size_t)wr * ld + k0 + lc);
        }
    };

    prefetch(0);
    asm volatile("cp.async.commit_group;");

    #pragma unroll 1
    for (int i = 0; i < ntot; i++) {
        if (i + 1 < ntot) prefetch(i + 1);
        asm volatile("cp.async.commit_group;");
        asm volatile("cp.async.wait_group 1;");
        __syncthreads();

        const uint32_t stg = smb + (uint32_t)(i & 1) * STAGE_SB;
        const int ph = (i >= nch0);

        #pragma unroll
        for (int s = 0; s < 2; s++) {
            const uint32_t ka = (uint32_t)s * 32;
            uint32_t ah[4], al[4];
            ldsm4(ah, stg + 0 * TILE_SB + aoff + ka);
            ldsm4(al, stg + 1 * TILE_SB + aoff + ka);
            #pragma unroll
            for (int g = 0; g < 3; g++) {
                const int ag = (ph && g == 2) ? 3 : g;
                #pragma unroll
                for (int pair = 0; pair < 2; pair++) {
                    uint32_t bh[4], bl[4];
                    uint32_t ba = stg + (2 + g * 2) * TILE_SB + boff + (uint32_t)pair * 1280 + ka;
                    ldsm4(bh, ba);
                    ldsm4(bl, ba + TILE_SB);
                    float* A0 = acc[ag] + pair * 8;
                    mma16816(A0,     ah, bh[0], bh[1]);
                    mma16816(A0 + 4, ah, bh[2], bh[3]);
                    mma16816(A0,     ah, bl[0], bl[1]);
                    mma16816(A0 + 4, ah, bl[2], bl[3]);
                    mma16816(A0,     al, bh[0], bh[1]);
                    mma16816(A0 + 4, al, bh[2], bh[3]);
                }
            }
        }
        __syncthreads();
    }

    // ---- epilogue: gates + output ----
    const int mrow = row0 + warp_m * 16 + (lane >> 2);
    const int colbase = c0 + warp_n * 32 + (lane & 3) * 2;
    #pragma unroll
    for (int half = 0; half < 2; half++) {
        int m = mrow + half * 8;
        int orow = out_rows ? out_rows[m] : m;
        const float* hrow = Hf + (size_t)m * 256;
        float* op = Out + (size_t)orow * 256;
        #pragma unroll
        for (int nt = 0; nt < 4; nt++) {
            #pragma unroll
            for (int e = 0; e < 2; e++) {
                int col = colbase + nt * 8 + e;
                int d = nt * 4 + half * 2 + e;
                float ar = acc[0][d] + bih[col] + bhh[col];
                float az = acc[1][d] + bih[256 + col] + bhh[256 + col];
                float r = 1.f / (1.f + expf(-ar));
                float z = 1.f / (1.f + expf(-az));
                float n = tanhf(acc[2][d] + bih[512 + col] + r * (acc[3][d] + bhh[512 + col]));
                op[col] = (1.f - z) * n + z * hrow[col];
            }
        }
    }
}

// ================= launch =================
extern "C" void kernel_launch(void* const* d_in, const int* in_sizes, int n_in,
                              void* d_out, int out_size) {
    const float* U      = (const float*)d_in[0];
    const float* qmask  = (const float*)d_in[1];
    const float* g_hist = (const float*)d_in[2];
    const float* q0     = (const float*)d_in[3];
    const float* r0     = (const float*)d_in[4];
    const float* e0     = (const float*)d_in[5];
    const float* g_wih  = (const float*)d_in[6];
    const float* g_whh  = (const float*)d_in[7];
    const float* g_bih  = (const float*)d_in[8];
    const float* g_bhh  = (const float*)d_in[9];
    const float* p_wih  = (const float*)d_in[10];
    const float* p_whh  = (const float*)d_in[11];
    const float* p_bih  = (const float*)d_in[12];
    const float* p_bhh  = (const float*)d_in[13];
    const float* pl_wih = (const float*)d_in[14];
    const float* pl_whh = (const float*)d_in[15];
    const float* pl_bih = (const float*)d_in[16];
    const float* pl_bhh = (const float*)d_in[17];
    const float* r_wih  = (const float*)d_in[18];
    const float* r_whh  = (const float*)d_in[19];
    const float* r_bih  = (const float*)d_in[20];
    const float* r_bhh  = (const float*)d_in[21];
    const float* e_wih  = (const float*)d_in[22];
    const float* e_whh  = (const float*)d_in[23];
    const float* e_bih  = (const float*)d_in[24];
    const float* e_bhh  = (const float*)d_in[25];
    const float* att_w  = (const float*)d_in[26];

    float* out = (float*)d_out;
    float* o_g = out;
    float* o_q = out + 1048576;
    float* o_r = out + 3145728;
    float* o_e = out + 5242880;
    float* o_a = out + 6291456;

    void* poolv;
    cudaGetSymbolAddress(&poolv, g_pool);
    char* pool = (char*)poolv;
    #define BF(off) ((__nv_bfloat16*)(pool + (off)))
    #define FP(off) ((float*)(pool + (off)))
    int* selrow = (int*)(pool + O_SELROW);
    int* qmidx  = (int*)(pool + O_QMIDX);

    cudaFuncSetAttribute(att_kernel, cudaFuncAttributeMaxDynamicSharedMemorySize,
                         TT * DD * (int)sizeof(float));
    cudaFuncSetAttribute(gru_mma_kernel, cudaFuncAttributeMaxDynamicSharedMemorySize, GRU_SMEM);

    // weight + state conversions (independent)
    conv_kernel<<<(768 * 768 + 255) / 256, 256>>>(g_wih,  BF(O_WGIH_H), BF(O_WGIH_L), 768 * 768);
    conv_kernel<<<(768 * 256 + 255) / 256, 256>>>(g_whh,  BF(O_WGHH_H), BF(O_WGHH_L), 768 * 256);
    conv_kernel<<<(768 * 512 + 255) / 256, 256>>>(p_wih,  BF(O_WPIH_H), BF(O_WPIH_L), 768 * 512);
    conv_kernel<<<(768 * 256 + 255) / 256, 256>>>(p_whh,  BF(O_WPHH_H), BF(O_WPHH_L), 768 * 256);
    conv_kernel<<<(768 * 512 + 255) / 256, 256>>>(pl_wih, BF(O_WLIH_H), BF(O_WLIH_L), 768 * 512);
    conv_kernel<<<(768 * 256 + 255) / 256, 256>>>(pl_whh, BF(O_WLHH_H), BF(O_WLHH_L), 768 * 256);
    conv_kernel<<<(768 * 512 + 255) / 256, 256>>>(r_wih,  BF(O_WRIH_H), BF(O_WRIH_L), 768 * 512);
    conv_kernel<<<(768 * 256 + 255) / 256, 256>>>(r_whh,  BF(O_WRHH_H), BF(O_WRHH_L), 768 * 256);
    conv_kernel<<<(768 * 768 + 255) / 256, 256>>>(e_wih,  BF(O_WEIH_H), BF(O_WEIH_L), 768 * 768);
    conv_kernel<<<(768 * 256 + 255) / 256, 256>>>(e_whh,  BF(O_WEHH_H), BF(O_WEHH_L), 768 * 256);
    conv_kernel<<<(2 * BB * 256 + 255) / 256, 256>>>(q0, BF(O_Q0_H), BF(O_Q0_L), 2 * BB * 256);
    conv_kernel<<<(BB * 256 + 255) / 256, 256>>>(g_hist + (size_t)63 * BB * DD, BF(O_GH_H), BF(O_GH_L), BB * 256);
    conv_kernel<<<(BB * 256 + 255) / 256, 256>>>(e0, BF(O_E0_H), BF(O_E0_L), BB * 256);

    // prep: qm_idx, selections, xg
    prep_kernel<<<BB, 256>>>(U, qmask, q0, r0,
        FP(O_QSF), FP(O_RSF), BF(O_QS_H), BF(O_QS_L), BF(O_RS_H), BF(O_RS_L),
        BF(O_XG_H), BF(O_XG_L), selrow, qmidx);

    // attention -> cvec, alpha
    att_kernel<<<BB, 256, TT * DD * sizeof(float)>>>(g_hist, att_w, FP(O_CV), o_a);

    // g GRU: K=768
    gru_mma_kernel<<<dim3(BB / 64, 4), 256, GRU_SMEM>>>(
        BF(O_XG_H), BF(O_XG_L), 768, 0,
        BF(O_GH_H), BF(O_GH_L), g_hist + (size_t)63 * BB * DD,
        BF(O_WGIH_H), BF(O_WGIH_L), BF(O_WGHH_H), BF(O_WGHH_L),
        g_bih, g_bhh, o_g, nullptr);

    // qs GRU: X per-b (xshift=1), 8192 rows
    build2b_kernel<<<dim3(BB, 2), 256>>>(BF(O_XQS_H), BF(O_XQS_L), o_g, U);
    gru_mma_kernel<<<dim3(2 * BB / 64, 4), 256, GRU_SMEM>>>(
        BF(O_XQS_H), BF(O_XQS_L), 512, 1,
        BF(O_Q0_H), BF(O_Q0_L), q0,
        BF(O_WPIH_H), BF(O_WPIH_L), BF(O_WPHH_H), BF(O_WPHH_L),
        p_bih, p_bhh, o_q, nullptr);

    // rs GRU (selected rows), scatter
    build2b_kernel<<<dim3(BB, 2), 256>>>(BF(O_XRS_H), BF(O_XRS_L), FP(O_CV), U);
    gru_mma_kernel<<<dim3(BB / 64, 4), 256, GRU_SMEM>>>(
        BF(O_XRS_H), BF(O_XRS_L), 512, 0,
        BF(O_RS_H), BF(O_RS_L), FP(O_RSF),
        BF(O_WRIH_H), BF(O_WRIH_L), BF(O_WRHH_H), BF(O_WRHH_L),
        r_bih, r_bhh, o_r, selrow);
    zero_r_kernel<<<BB, 256>>>(o_r, qmidx);

    // ql GRU (selected rows), scatter into q_
    build_xplb_kernel<<<dim3(BB, 2), 256>>>(BF(O_XPL_H), BF(O_XPL_L), o_q, U, selrow);
    gru_mma_kernel<<<dim3(BB / 64, 4), 256, GRU_SMEM>>>(
        BF(O_XPL_H), BF(O_XPL_L), 512, 0,
        BF(O_QS_H), BF(O_QS_L), FP(O_QSF),
        BF(O_WLIH_H), BF(O_WLIH_L), BF(O_WLHH_H), BF(O_WLHH_L),
        pl_bih, pl_bhh, o_q, selrow);

    // e GRU: K=768
    build_xeb_kernel<<<dim3(BB, 3), 256>>>(BF(O_XE_H), BF(O_XE_L), U, o_q, o_g, selrow);
    gru_mma_kernel<<<dim3(BB / 64, 4), 256, GRU_SMEM>>>(
        BF(O_XE_H), BF(O_XE_L), 768, 0,
        BF(O_E0_H), BF(O_E0_L), e0,
        BF(O_WEIH_H), BF(O_WEIH_L), BF(O_WEHH_H), BF(O_WEHH_L),
        e_bih, e_bhh, o_e, nullptr);
    #undef BF
    #undef FP
}

// round 7
// speedup vs baseline: 1.5476x; 1.0224x over previous
#include <cuda_runtime.h>
#include <cuda_bf16.h>
#include <math.h>
#include <stdint.h>

#define BB 4096
#define DD 256
#define TT 64

// ================= PTX helpers (baseline ISA only) =================
__device__ __forceinline__ uint32_t smem_u32(const void* p) {
    uint32_t a;
    asm("{ .reg .u64 t; cvta.to.shared.u64 t, %1; cvt.u32.u64 %0, t; }" : "=r"(a) : "l"(p));
    return a;
}
__device__ __forceinline__ void cp16(uint32_t saddr, const void* g) {
    asm volatile("cp.async.cg.shared.global [%0], [%1], 16;" :: "r"(saddr), "l"(g));
}
__device__ __forceinline__ void ldsm4(uint32_t* r, uint32_t addr) {
    asm volatile("ldmatrix.sync.aligned.m8n8.x4.shared.b16 {%0,%1,%2,%3}, [%4];"
        : "=r"(r[0]), "=r"(r[1]), "=r"(r[2]), "=r"(r[3]) : "r"(addr));
}
__device__ __forceinline__ void mma16816(float* c, const uint32_t* a, uint32_t b0, uint32_t b1) {
    asm volatile("mma.sync.aligned.m16n8k16.row.col.f32.bf16.bf16.f32 "
        "{%0,%1,%2,%3}, {%4,%5,%6,%7}, {%8,%9}, {%0,%1,%2,%3};"
        : "+f"(c[0]), "+f"(c[1]), "+f"(c[2]), "+f"(c[3])
        : "r"(a[0]), "r"(a[1]), "r"(a[2]), "r"(a[3]), "r"(b0), "r"(b1));
}

// ================= scratch pool =================
static constexpr size_t SZ_XG  = (size_t)BB * 768 * 2;
static constexpr size_t SZ_XS  = (size_t)BB * 512 * 2;
static constexpr size_t SZ_BD  = (size_t)BB * 256 * 2;
static constexpr size_t SZ_Q0  = (size_t)2 * BB * 256 * 2;
static constexpr size_t SZ_BDF = (size_t)BB * 256 * 4;

static constexpr size_t O_XG_H  = 0;
static constexpr size_t O_XG_L  = O_XG_H  + SZ_XG;
static constexpr size_t O_XE_H  = O_XG_L  + SZ_XG;
static constexpr size_t O_XE_L  = O_XE_H  + SZ_XG;
static constexpr size_t O_XQS_H = O_XE_L  + SZ_XG;
static constexpr size_t O_XQS_L = O_XQS_H + SZ_XS;
static constexpr size_t O_XRS_H = O_XQS_L + SZ_XS;
static constexpr size_t O_XRS_L = O_XRS_H + SZ_XS;
static constexpr size_t O_XPL_H = O_XRS_L + SZ_XS;
static constexpr size_t O_XPL_L = O_XPL_H + SZ_XS;
static constexpr size_t O_Q0_H  = O_XPL_L + SZ_XS;
static constexpr size_t O_Q0_L  = O_Q0_H  + SZ_Q0;
static constexpr size_t O_GH_H  = O_Q0_L  + SZ_Q0;
static constexpr size_t O_GH_L  = O_GH_H  + SZ_BD;
static constexpr size_t O_E0_H  = O_GH_L  + SZ_BD;
static constexpr size_t O_E0_L  = O_E0_H  + SZ_BD;
static constexpr size_t O_QS_H  = O_E0_L  + SZ_BD;
static constexpr size_t O_QS_L  = O_QS_H  + SZ_BD;
static constexpr size_t O_RS_H  = O_QS_L  + SZ_BD;
static constexpr size_t O_RS_L  = O_RS_H  + SZ_BD;
static constexpr size_t O_QSF   = O_RS_L  + SZ_BD;
static constexpr size_t O_RSF   = O_QSF   + SZ_BDF;
static constexpr size_t SZ_W768 = (size_t)768 * 768 * 2;
static constexpr size_t SZ_W512 = (size_t)768 * 512 * 2;
static constexpr size_t SZ_W256 = (size_t)768 * 256 * 2;
static constexpr size_t O_WGIH_H = O_RSF + SZ_BDF;
static constexpr size_t O_WGIH_L = O_WGIH_H + SZ_W768;
static constexpr size_t O_WGHH_H = O_WGIH_L + SZ_W768;
static constexpr size_t O_WGHH_L = O_WGHH_H + SZ_W256;
static constexpr size_t O_WPIH_H = O_WGHH_L + SZ_W256;
static constexpr size_t O_WPIH_L = O_WPIH_H + SZ_W512;
static constexpr size_t O_WPHH_H = O_WPIH_L + SZ_W512;
static constexpr size_t O_WPHH_L = O_WPHH_H + SZ_W256;
static constexpr size_t O_WLIH_H = O_WPHH_L + SZ_W256;
static constexpr size_t O_WLIH_L = O_WLIH_H + SZ_W512;
static constexpr size_t O_WLHH_H = O_WLIH_L + SZ_W512;
static constexpr size_t O_WLHH_L = O_WLHH_H + SZ_W256;
static constexpr size_t O_WRIH_H = O_WLHH_L + SZ_W256;
static constexpr size_t O_WRIH_L = O_WRIH_H + SZ_W512;
static constexpr size_t O_WRHH_H = O_WRIH_L + SZ_W512;
static constexpr size_t O_WRHH_L = O_WRHH_H + SZ_W256;
static constexpr size_t O_WEIH_H = O_WRHH_L + SZ_W256;
static constexpr size_t O_WEIH_L = O_WEIH_H + SZ_W768;
static constexpr size_t O_WEHH_H = O_WEIH_L + SZ_W768;
static constexpr size_t O_WEHH_L = O_WEHH_H + SZ_W256;
static constexpr size_t O_SELROW = O_WEHH_L + SZ_W256;
static constexpr size_t O_QMIDX  = O_SELROW + BB * 4;
static constexpr size_t POOL_SZ  = O_QMIDX + BB * 4;

__device__ __align__(1024) unsigned char g_pool[POOL_SZ];

// ================= helpers =================
__device__ __forceinline__ void bsplit(float x, __nv_bfloat16* hp, __nv_bfloat16* lp, size_t i) {
    __nv_bfloat16 h = __float2bfloat16(x);
    hp[i] = h;
    lp[i] = __float2bfloat16(x - __bfloat162float(h));
}

// ================= conv_all: all f32->bf16 hi/lo conversions in ONE kernel =======
struct ConvSeg { const float* src; __nv_bfloat16* hi; __nv_bfloat16* lo; int nblk; };
struct ConvTable { ConvSeg s[13]; };

__global__ void conv_all_kernel(ConvTable t) {
    int blk = blockIdx.x;
    #pragma unroll 1
    for (int i = 0; i < 13; i++) {
        int nb = t.s[i].nblk;
        if (blk < nb) {
            int idx = blk * 256 + threadIdx.x;
            bsplit(t.s[i].src[idx], t.s[i].hi, t.s[i].lo, idx);
            return;
        }
        blk -= nb;
    }
}

// ================= prep: gathers + all static input segments =================
__global__ void prep_kernel(const float* __restrict__ U, const float* __restrict__ qmask,
                            const float* __restrict__ q0, const float* __restrict__ r0,
                            float* __restrict__ qsf, float* __restrict__ rsf,
                            __nv_bfloat16* qsh, __nv_bfloat16* qsl,
                            __nv_bfloat16* rsh, __nv_bfloat16* rsl,
                            __nv_bfloat16* xgh, __nv_bfloat16* xgl,
                            __nv_bfloat16* xqsh, __nv_bfloat16* xqsl,
                            __nv_bfloat16* xrsh, __nv_bfloat16* xrsl,
                            __nv_bfloat16* xplh, __nv_bfloat16* xpll,
                            __nv_bfloat16* xeh,  __nv_bfloat16* xel,
                            int* __restrict__ selrow, int* __restrict__ qmidx) {
    int i = blockIdx.x * 256 + threadIdx.x;
    int b = i >> 8, d = i & 255;
    int qm = (qmask[b * 2 + 1] > qmask[b * 2]) ? 1 : 0;
    if (d == 0) { qmidx[b] = qm; selrow[b] = b * 2 + qm; }
    float q = q0[(size_t)(b * 2 + qm) * DD + d];
    float r = r0[(size_t)(b * 2 + qm) * DD + d];
    float u = U[i];
    qsf[i] = q; rsf[i] = r;
    bsplit(q, qsh, qsl, i);
    bsplit(r, rsh, rsl, i);
    size_t o = (size_t)b * 768 + d;
    bsplit(q, xgh, xgl, o);
    bsplit(r, xgh, xgl, o + 256);
    bsplit(u, xgh, xgl, o + 512);
    // U halves for downstream GRU inputs
    size_t o2 = (size_t)b * 512 + 256 + d;
    bsplit(u, xqsh, xqsl, o2);
    bsplit(u, xrsh, xrsl, o2);
    bsplit(u, xplh, xpll, o2);
    bsplit(u, xeh, xel, o);   // xe seg0 = U
}

// ================= attention: writes context directly into xrs (bf16 hi/lo) =====
__global__ void att_kernel(const float* __restrict__ gh, const float* __restrict__ attw,
                           __nv_bfloat16* __restrict__ xrsh, __nv_bfloat16* __restrict__ xrsl,
                           float* __restrict__ alpha_out) {
    extern __shared__ float sh[];
    __shared__ float s_aw[DD];
    __shared__ float s_scale[TT];
    __shared__ float s_alpha[TT];
    int b = blockIdx.x, tid = threadIdx.x;
    s_aw[tid] = attw[tid];
    for (int t = 0; t < TT; t++)
        sh[t * DD + tid] = gh[((size_t)t * BB + b) * DD + tid];
    __syncthreads();
    int w = tid >> 5, lane = tid & 31;
    for (int t = w; t < TT; t += 8) {
        float s = 0.f;
        #pragma unroll
        for (int i = 0; i < 8; i++) s += sh[t * DD + lane + i * 32] * s_aw[lane + i * 32];
        #pragma unroll
        for (int o = 16; o > 0; o >>= 1) s += __shfl_down_sync(0xffffffffu, s, o);
        if (lane == 0) s_scale[t] = s;
    }
    __syncthreads();
    if (w == 0) {
        float v0 = s_scale[lane], v1 = s_scale[lane + 32];
        float m = fmaxf(v0, v1);
        #pragma unroll
        for (int o = 16; o > 0; o >>= 1) m = fmaxf(m, __shfl_xor_sync(0xffffffffu, m, o));
        float e0 = expf(v0 - m), e1 = expf(v1 - m);
        float s = e0 + e1;
        #pragma unroll
        for (int o = 16; o > 0; o >>= 1) s += __shfl_xor_sync(0xffffffffu, s, o);
        float inv = 1.f / s;
        s_alpha[lane] = e0 * inv;
        s_alpha[lane + 32] = e1 * inv;
        alpha_out[(size_t)b * TT + lane] = e0 * inv;
        alpha_out[(size_t)b * TT + lane + 32] = e1 * inv;
    }
    __syncthreads();
    float acc = 0.f;
    for (int t = 0; t < TT; t++) acc += s_alpha[t] * sh[t * DD + tid];
    bsplit(acc, xrsh, xrsl, (size_t)b * 512 + tid);
}

// ================= fused GRU via mma.sync (bf16 3-term split) =================
#define TILE_SB 5120
#define STAGE_SB (8 * TILE_SB)
#define GRU_SMEM (2 * STAGE_SB)

__global__ __launch_bounds__(256, 2) void gru_mma_kernel(
    const __nv_bfloat16* __restrict__ Xhi, const __nv_bfloat16* __restrict__ Xlo,
    int K, int xshift,
    const __nv_bfloat16* __restrict__ Hhi, const __nv_bfloat16* __restrict__ Hlo,
    const float* __restrict__ Hf,
    const __nv_bfloat16* __restrict__ Wih_hi, const __nv_bfloat16* __restrict__ Wih_lo,
    const __nv_bfloat16* __restrict__ Whh_hi, const __nv_bfloat16* __restrict__ Whh_lo,
    const float* __restrict__ bih, const float* __restrict__ bhh,
    float* __restrict__ Out, const int* __restrict__ out_rows,
    const int* __restrict__ selrow, int zero_other,
    __nv_bfloat16* __restrict__ x1h, __nv_bfloat16* __restrict__ x1l,
    int x1_stride, int x1_off, int x1_sel,
    __nv_bfloat16* __restrict__ x2h, __nv_bfloat16* __restrict__ x2l,
    int x2_stride, int x2_off)
{
    extern __shared__ __align__(16) char dsm[];
    const uint32_t smb = smem_u32(dsm);

    const int tid = threadIdx.x;
    const int wid = tid >> 5, lane = tid & 31;
    const int warp_m = wid & 3, warp_n = wid >> 2;
    const int row0 = blockIdx.x * 64, c0 = blockIdx.y * 64;

    const int lr = tid >> 2;
    const int lc = (tid & 3) * 8;
    const uint32_t st_off = (uint32_t)lr * 80 + (tid & 3) * 16;

    const int nch0 = K / 32;
    const int ntot = nch0 + 8;

    float acc[4][16];
    #pragma unroll
    for (int g = 0; g < 4; g++)
        #pragma unroll
        for (int d = 0; d < 16; d++) acc[g][d] = 0.f;

    const uint32_t aoff = ((uint32_t)(warp_m * 16 + (lane & 7) + ((lane >> 3) & 1) * 8)) * 80
                        + (uint32_t)(lane >> 4) * 16;
    const uint32_t boff = ((uint32_t)(warp_n * 32 + (lane & 7) + (lane >> 4) * 8)) * 80
                        + (uint32_t)((lane >> 3) & 1) * 16;

    auto prefetch = [&](int idx) {
        const __nv_bfloat16 *ah, *al, *wh, *wl;
        int ld, k0, sh;
        if (idx < nch0) { ah = Xhi; al = Xlo; wh = Wih_hi; wl = Wih_lo; ld = K;   k0 = idx * 32;          sh = xshift; }
        else            { ah = Hhi; al = Hlo; wh = Whh_hi; wl = Whh_lo; ld = 256; k0 = (idx - nch0) * 32; sh = 0; }
        uint32_t stg = smb + (uint32_t)(idx & 1) * STAGE_SB;
        int xr = (row0 + lr) >> sh;
        cp16(stg + 0 * TILE_SB + st_off, ah + (size_t)xr * ld + k0 + lc);
        cp16(stg + 1 * TILE_SB + st_off, al + (size_t)xr * ld + k0 + lc);
        #pragma unroll
        for (int g = 0; g < 3; g++) {
            int wr = g * 256 + c0 + lr;
            cp16(stg + (2 + g * 2) * TILE_SB + st_off, wh + (size_t)wr * ld + k0 + lc);
            cp16(stg + (3 + g * 2) * TILE_SB + st_off, wl + (size_t)wr * ld + k0 + lc);
        }
    };

    prefetch(0);
    asm volatile("cp.async.commit_group;");

    #pragma unroll 1
    for (int i = 0; i < ntot; i++) {
        if (i + 1 < ntot) prefetch(i + 1);
        asm volatile("cp.async.commit_group;");
        asm volatile("cp.async.wait_group 1;");
        __syncthreads();

        const uint32_t stg = smb + (uint32_t)(i & 1) * STAGE_SB;
        const int ph = (i >= nch0);

        #pragma unroll
        for (int s = 0; s < 2; s++) {
            const uint32_t ka = (uint32_t)s * 32;
            uint32_t ah[4], al[4];
            ldsm4(ah, stg + 0 * TILE_SB + aoff + ka);
            ldsm4(al, stg + 1 * TILE_SB + aoff + ka);
            #pragma unroll
            for (int g = 0; g < 3; g++) {
                const int ag = (ph && g == 2) ? 3 : g;
                #pragma unroll
                for (int pair = 0; pair < 2; pair++) {
                    uint32_t bh[4], bl[4];
                    uint32_t ba = stg + (2 + g * 2) * TILE_SB + boff + (uint32_t)pair * 1280 + ka;
                    ldsm4(bh, ba);
                    ldsm4(bl, ba + TILE_SB);
                    float* A0 = acc[ag] + pair * 8;
                    mma16816(A0,     ah, bh[0], bh[1]);
                    mma16816(A0 + 4, ah, bh[2], bh[3]);
                    mma16816(A0,     ah, bl[0], bl[1]);
                    mma16816(A0 + 4, ah, bl[2], bl[3]);
                    mma16816(A0,     al, bh[0], bh[1]);
                    mma16816(A0 + 4, al, bh[2], bh[3]);
                }
            }
        }
        __syncthreads();
    }

    // ---- epilogue: gates + output + fused next-input writes ----
    const int mrow = row0 + warp_m * 16 + (lane >> 2);
    const int colbase = c0 + warp_n * 32 + (lane & 3) * 2;
    #pragma unroll
    for (int half = 0; half < 2; half++) {
        int m = mrow + half * 8;
        int orow = out_rows ? out_rows[m] : m;
        const float* hrow = Hf + (size_t)m * 256;
        float* op = Out + (size_t)orow * 256;
        float* oo = zero_other ? (Out + (size_t)(orow ^ 1) * 256) : nullptr;
        int x1b = x1_sel ? (m >> 1) : m;
        bool x1ok = x1h && (!x1_sel || (selrow[x1b] == m));
        #pragma unroll
        for (int nt = 0; nt < 4; nt++) {
            #pragma unroll
            for (int e = 0; e < 2; e++) {
                int col = colbase + nt * 8 + e;
                int d = nt * 4 + half * 2 + e;
                float ar = acc[0][d] + bih[col] + bhh[col];
                float az = acc[1][d] + bih[256 + col] + bhh[256 + col];
                float r = 1.f / (1.f + expf(-ar));
                float z = 1.f / (1.f + expf(-az));
                float n = tanhf(acc[2][d] + bih[512 + col] + r * (acc[3][d] + bhh[512 + col]));
                float v = (1.f - z) * n + z * hrow[col];
                op[col] = v;
                if (oo) oo[col] = 0.f;
                if (x1ok) bsplit(v, x1h, x1l, (size_t)x1b * x1_stride + x1_off + col);
                if (x2h)  bsplit(v, x2h, x2l, (size_t)m * x2_stride + x2_off + col);
            }
        }
    }
}

// ================= launch =================
extern "C" void kernel_launch(void* const* d_in, const int* in_sizes, int n_in,
                              void* d_out, int out_size) {
    const float* U      = (const float*)d_in[0];
    const float* qmask  = (const float*)d_in[1];
    const float* g_hist = (const float*)d_in[2];
    const float* q0     = (const float*)d_in[3];
    const float* r0     = (const float*)d_in[4];
    const float* e0     = (const float*)d_in[5];
    const float* g_wih  = (const float*)d_in[6];
    const float* g_whh  = (const float*)d_in[7];
    const float* g_bih  = (const float*)d_in[8];
    const float* g_bhh  = (const float*)d_in[9];
    const float* p_wih  = (const float*)d_in[10];
    const float* p_whh  = (const float*)d_in[11];
    const float* p_bih  = (const float*)d_in[12];
    const float* p_bhh  = (const float*)d_in[13];
    const float* pl_wih = (const float*)d_in[14];
    const float* pl_whh = (const float*)d_in[15];
    const float* pl_bih = (const float*)d_in[16];
    const float* pl_bhh = (const float*)d_in[17];
    const float* r_wih  = (const float*)d_in[18];
    const float* r_whh  = (const float*)d_in[19];
    const float* r_bih  = (const float*)d_in[20];
    const float* r_bhh  = (const float*)d_in[21];
    const float* e_wih  = (const float*)d_in[22];
    const float* e_whh  = (const float*)d_in[23];
    const float* e_bih  = (const float*)d_in[24];
    const float* e_bhh  = (const float*)d_in[25];
    const float* att_w  = (const float*)d_in[26];

    float* out = (float*)d_out;
    float* o_g = out;
    float* o_q = out + 1048576;
    float* o_r = out + 3145728;
    float* o_e = out + 5242880;
    float* o_a = out + 6291456;

    void* poolv;
    cudaGetSymbolAddress(&poolv, g_pool);
    char* pool = (char*)poolv;
    #define BF(off) ((__nv_bfloat16*)(pool + (off)))
    #define FP(off) ((float*)(pool + (off)))
    int* selrow = (int*)(pool + O_SELROW);
    int* qmidx  = (int*)(pool + O_QMIDX);

    cudaFuncSetAttribute(att_kernel, cudaFuncAttributeMaxDynamicSharedMemorySize,
                         TT * DD * (int)sizeof(float));
    cudaFuncSetAttribute(gru_mma_kernel, cudaFuncAttributeMaxDynamicSharedMemorySize, GRU_SMEM);

    const float* ghl = g_hist + (size_t)63 * BB * DD;

    // 1) all conversions in one kernel
    ConvTable ct;
    int ti = 0, total_blk = 0;
    auto addseg = [&](const float* s, size_t oh, size_t ol, int n) {
        ct.s[ti].src = s; ct.s[ti].hi = BF(oh); ct.s[ti].lo = BF(ol);
        ct.s[ti].nblk = n / 256; total_blk += n / 256; ti++;
    };
    addseg(g_wih,  O_WGIH_H, O_WGIH_L, 768 * 768);
    addseg(g_whh,  O_WGHH_H, O_WGHH_L, 768 * 256);
    addseg(p_wih,  O_WPIH_H, O_WPIH_L, 768 * 512);
    addseg(p_whh,  O_WPHH_H, O_WPHH_L, 768 * 256);
    addseg(pl_wih, O_WLIH_H, O_WLIH_L, 768 * 512);
    addseg(pl_whh, O_WLHH_H, O_WLHH_L, 768 * 256);
    addseg(r_wih,  O_WRIH_H, O_WRIH_L, 768 * 512);
    addseg(r_whh,  O_WRHH_H, O_WRHH_L, 768 * 256);
    addseg(e_wih,  O_WEIH_H, O_WEIH_L, 768 * 768);
    addseg(e_whh,  O_WEHH_H, O_WEHH_L, 768 * 256);
    addseg(q0,     O_Q0_H,   O_Q0_L,   2 * BB * 256);
    addseg(ghl,    O_GH_H,   O_GH_L,   BB * 256);
    addseg(e0,     O_E0_H,   O_E0_L,   BB * 256);
    conv_all_kernel<<<total_blk, 256>>>(ct);

    // 2) prep: gathers, xg, U-halves of xqs/xrs/xpl/xe
    prep_kernel<<<BB, 256>>>(U, qmask, q0, r0,
        FP(O_QSF), FP(O_RSF), BF(O_QS_H), BF(O_QS_L), BF(O_RS_H), BF(O_RS_L),
        BF(O_XG_H), BF(O_XG_L),
        BF(O_XQS_H), BF(O_XQS_L), BF(O_XRS_H), BF(O_XRS_L),
        BF(O_XPL_H), BF(O_XPL_L), BF(O_XE_H), BF(O_XE_L),
        selrow, qmidx);

    // 3) attention -> xrs first half (bf16) + alpha
    att_kernel<<<BB, 256, TT * DD * sizeof(float)>>>(g_hist, att_w,
        BF(O_XRS_H), BF(O_XRS_L), o_a);

    // 4) g GRU: K=768; epilogue also writes xqs[0:256] and xe[512:768]
    gru_mma_kernel<<<dim3(BB / 64, 4), 256, GRU_SMEM>>>(
        BF(O_XG_H), BF(O_XG_L), 768, 0,
        BF(O_GH_H), BF(O_GH_L), ghl,
        BF(O_WGIH_H), BF(O_WGIH_L), BF(O_WGHH_H), BF(O_WGHH_L),
        g_bih, g_bhh, o_g, nullptr,
        nullptr, 0,
        BF(O_XQS_H), BF(O_XQS_L), 512, 0, 0,
        BF(O_XE_H), BF(O_XE_L), 768, 512);

    // 5) qs GRU: 8192 rows; epilogue writes xpl[0:256] for selected rows
    gru_mma_kernel<<<dim3(2 * BB / 64, 4), 256, GRU_SMEM>>>(
        BF(O_XQS_H), BF(O_XQS_L), 512, 1,
        BF(O_Q0_H), BF(O_Q0_L), q0,
        BF(O_WPIH_H), BF(O_WPIH_L), BF(O_WPHH_H), BF(O_WPHH_L),
        p_bih, p_bhh, o_q, nullptr,
        selrow, 0,
        BF(O_XPL_H), BF(O_XPL_L), 512, 0, 1,
        nullptr, nullptr, 0, 0);

    // 6) rs GRU (selected rows), scatter + zero sibling row   [ncu slot 6]
    gru_mma_kernel<<<dim3(BB / 64, 4), 256, GRU_SMEM>>>(
        BF(O_XRS_H), BF(O_XRS_L), 512, 0,
        BF(O_RS_H), BF(O_RS_L), FP(O_RSF),
        BF(O_WRIH_H), BF(O_WRIH_L), BF(O_WRHH_H), BF(O_WRHH_L),
        r_bih, r_bhh, o_r, selrow,
        nullptr, 1,
        nullptr, nullptr, 0, 0, 0,
        nullptr, nullptr, 0, 0);

    // 7) ql GRU (selected rows), scatter into q_; epilogue writes xe[256:512]
    gru_mma_kernel<<<dim3(BB / 64, 4), 256, GRU_SMEM>>>(
        BF(O_XPL_H), BF(O_XPL_L), 512, 0,
        BF(O_QS_H), BF(O_QS_L), FP(O_QSF),
        BF(O_WLIH_H), BF(O_WLIH_L), BF(O_WLHH_H), BF(O_WLHH_L),
        pl_bih, pl_bhh, o_q, selrow,
        nullptr, 0,
        BF(O_XE_H), BF(O_XE_L), 768, 256, 0,
        nullptr, nullptr, 0, 0);

    // 8) e GRU: K=768
    gru_mma_kernel<<<dim3(BB / 64, 4), 256, GRU_SMEM>>>(
        BF(O_XE_H), BF(O_XE_L), 768, 0,
        BF(O_E0_H), BF(O_E0_L), e0,
        BF(O_WEIH_H), BF(O_WEIH_L), BF(O_WEHH_H), BF(O_WEHH_L),
        e_bih, e_bhh, o_e, nullptr,
        nullptr, 0,
        nullptr, nullptr, 0, 0, 0,
        nullptr, nullptr, 0, 0);
    #undef BF
    #undef FP
}